// round 11
// baseline (speedup 1.0000x reference)
#include <cuda_runtime.h>
#include <cstddef>

// Problem constants (fixed by the dataset instance)
#define MM   4
#define AA   256
#define RBF  64
#define FF   32
#define HH   32
#define SI   32
#define CC   128   // 4 filters * FF radial columns

// Precombined radial weights, row-major over k: g_Wt[k*CC + c]
__device__ float g_Wt[RBF * CC];
__device__ float g_bias[CC];

struct Wptrs {
    const float* w1[4];
    const float* b1[4];
    const float* w2[4];
    const float* b2[4];
};

// ---------------------------------------------------------------------------
// Precompute W = w1 @ w2 (per filter), bias = b1 @ w2 + b2.
// g_Wt[k][c], c = filt*32 + f  (filt order: 00, 01, 10, 11).
// ---------------------------------------------------------------------------
__global__ void prep_kernel(Wptrs wp) {
    int idx = blockIdx.x * blockDim.x + threadIdx.x;
    if (idx < CC * RBF) {
        int c = idx & (CC - 1);
        int k = idx >> 7;
        int filt = c >> 5;
        int f = c & 31;
        const float* w1 = wp.w1[filt];
        const float* w2 = wp.w2[filt];
        float s = 0.f;
#pragma unroll
        for (int h = 0; h < HH; h++)
            s += w1[k * HH + h] * w2[h * FF + f];
        g_Wt[k * CC + c] = s;
        if (k == 0) {
            float bs = wp.b2[filt][f];
            const float* b1 = wp.b1[filt];
#pragma unroll
            for (int h = 0; h < HH; h++)
                bs += b1[h] * w2[h * FF + f];
            g_bias[c] = bs;
        }
    }
}

// ---------------------------------------------------------------------------
// Packed fp32x2 helpers (Blackwell FFMA2 — PTX-only path)
// ---------------------------------------------------------------------------
typedef unsigned long long u64;

__device__ __forceinline__ u64 ffma2(u64 a, u64 b, u64 c) {
    u64 d;
    asm("fma.rn.f32x2 %0, %1, %2, %3;" : "=l"(d) : "l"(a), "l"(b), "l"(c));
    return d;
}
__device__ __forceinline__ u64 splat2(float x) {
    u64 d;
    asm("mov.b64 %0, {%1, %1};" : "=l"(d) : "f"(x));
    return d;
}
__device__ __forceinline__ float2 unpk(u64 a) {
    float2 r;
    asm("mov.b64 {%0, %1}, %2;" : "=f"(r.x), "=f"(r.y) : "l"(a));
    return r;
}
__device__ __forceinline__ float sspf(float x) {
    return logf(0.5f * expf(x) + 0.5f);   // shifted softplus
}

// ---------------------------------------------------------------------------
// Main fused kernel: one block per (m, a).  256 threads.
//   tc = tid>>3 (0..31): 4 radial columns c = 4*tc..4*tc+3 (one filter/warp)
//   tb = tid&7  (0..7) : 8 neighbor rows per 64-row chunk
// Radial GEMM is register-tiled 8b x 4c with packed f32x2 accumulators;
// image chunk lives transposed in smem (Ism[k][b]); W streamed via LDG.128.
// ---------------------------------------------------------------------------
__global__ void __launch_bounds__(256, 2) conv_kernel(
    const float* __restrict__ image,
    const float* __restrict__ vectors,
    const float* __restrict__ feat0,
    const float* __restrict__ feat1,
    const float* __restrict__ w_si0,
    const float* __restrict__ w_si1,
    const float* __restrict__ b_act0,
    const float* __restrict__ b_act1,
    float* __restrict__ out)
{
    const int ma  = blockIdx.x;        // m*AA + a
    const int m   = ma >> 8;
    const int tid = threadIdx.x;
    const int tc  = tid >> 3;          // 0..31 column group
    const int tb  = tid & 7;           // 0..7  b group
    const int filt  = tc >> 3;         // 0..3 (uniform within warp)
    const int fbase = (tc & 7) * 4;    // f of ci=0

    __shared__ __align__(16) float s_buf[RBF * 64];  // Ism[k][b]; later s_red
    __shared__ float s_v[64][4];
    __shared__ float s_cat[FF][12];

    float (*Ism)[64] = (float (*)[64])s_buf;

    const float* imgbase = image   + (size_t)ma * (AA * RBF);
    const float* vbase   = vectors + (size_t)ma * (AA * 3);
    const float* f0base  = feat0   + (size_t)m  * (AA * FF);
    const float* f1base  = feat1   + (size_t)m  * (AA * FF * 3);

    float bias[4];
    {
        float4 bb = *(const float4*)(g_bias + tc * 4);
        bias[0] = bb.x; bias[1] = bb.y; bias[2] = bb.z; bias[3] = bb.w;
    }

    float acc[4][4];
#pragma unroll
    for (int ci = 0; ci < 4; ci++)
#pragma unroll
        for (int sl = 0; sl < 4; sl++) acc[ci][sl] = 0.f;

    // ---- register-staged image/vector chunk staging ----
    const int sb  = tid & 63;          // b row within chunk
    const int skq = tid >> 6;          // which 16-k slice
    float4 sI[4];
    float  sv = 0.f;

    auto loadregs = [&](int chunk) {
        const float4* src = (const float4*)(imgbase +
            (size_t)(chunk * 64 + sb) * RBF + skq * 16);
#pragma unroll
        for (int j = 0; j < 4; j++) sI[j] = src[j];
        if (tid < 192) sv = vbase[chunk * 192 + tid];
    };
    auto stsregs = [&]() {
#pragma unroll
        for (int j = 0; j < 4; j++) {
            const int k0 = skq * 16 + j * 4;
            Ism[k0 + 0][sb] = sI[j].x;
            Ism[k0 + 1][sb] = sI[j].y;
            Ism[k0 + 2][sb] = sI[j].z;
            Ism[k0 + 3][sb] = sI[j].w;
        }
        if (tid < 192) s_v[tid / 3][tid % 3] = sv;
    };

    loadregs(0);
    stsregs();
    __syncthreads();

    const float* wbase = g_Wt + tc * 4;

    for (int chunk = 0; chunk < 4; chunk++) {
        if (chunk < 3) loadregs(chunk + 1);   // prefetch next chunk into regs

        // ---- 8b x 4c register-tiled GEMM over k=64 ----
        u64 t[4][4];
#pragma unroll
        for (int ci = 0; ci < 4; ci++)
#pragma unroll
            for (int bp = 0; bp < 4; bp++) t[ci][bp] = 0ULL;

#pragma unroll 8
        for (int k = 0; k < 64; k++) {
            float4 w4 = *(const float4*)(wbase + k * CC);       // LDG.128 (L1)
            const u64* ip = (const u64*)&Ism[k][tb * 8];        // 2x LDS.128
            u64 i0 = ip[0], i1 = ip[1], i2 = ip[2], i3 = ip[3];
            u64 w0 = splat2(w4.x), w1 = splat2(w4.y);
            u64 w2 = splat2(w4.z), w3 = splat2(w4.w);
            t[0][0] = ffma2(i0, w0, t[0][0]); t[0][1] = ffma2(i1, w0, t[0][1]);
            t[0][2] = ffma2(i2, w0, t[0][2]); t[0][3] = ffma2(i3, w0, t[0][3]);
            t[1][0] = ffma2(i0, w1, t[1][0]); t[1][1] = ffma2(i1, w1, t[1][1]);
            t[1][2] = ffma2(i2, w1, t[1][2]); t[1][3] = ffma2(i3, w1, t[1][3]);
            t[2][0] = ffma2(i0, w2, t[2][0]); t[2][1] = ffma2(i1, w2, t[2][1]);
            t[2][2] = ffma2(i2, w2, t[2][2]); t[2][3] = ffma2(i3, w2, t[2][3]);
            t[3][0] = ffma2(i0, w3, t[3][0]); t[3][1] = ffma2(i1, w3, t[3][1]);
            t[3][2] = ffma2(i2, w3, t[3][2]); t[3][3] = ffma2(i3, w3, t[3][3]);
        }

        // ---- immediate contraction over this chunk's 8 b rows ----
#pragma unroll
        for (int bp = 0; bp < 4; bp++) {
            float r[2][4];
#pragma unroll
            for (int ci = 0; ci < 4; ci++) {
                float2 u = unpk(t[ci][bp]);
                r[0][ci] = u.x + bias[ci];
                r[1][ci] = u.y + bias[ci];
            }
#pragma unroll
            for (int h = 0; h < 2; h++) {
                const int bl = tb * 8 + bp * 2 + h;
                const int b  = chunk * 64 + bl;

                if (filt == 0) {
                    // out_0x0_0: acc0 += r * feat0
                    float4 p = *(const float4*)(f0base + b * FF + fbase);
                    acc[0][0] += r[h][0] * p.x;
                    acc[1][0] += r[h][1] * p.y;
                    acc[2][0] += r[h][2] * p.z;
                    acc[3][0] += r[h][3] * p.w;
                } else if (filt == 1) {
                    // out_0x1_1: acc[0..2] += (r*mask)*feat0 * v
                    float vx = s_v[bl][0], vy = s_v[bl][1], vz = s_v[bl][2];
                    float n2 = vx * vx + vy * vy + vz * vz;
                    float mk = (n2 < 1e-14f) ? 0.f : 1.f;
                    float4 p = *(const float4*)(f0base + b * FF + fbase);
                    float pp[4] = {p.x, p.y, p.z, p.w};
#pragma unroll
                    for (int ci = 0; ci < 4; ci++) {
                        float tp = r[h][ci] * mk * pp[ci];
                        acc[ci][0] += tp * vx;
                        acc[ci][1] += tp * vy;
                        acc[ci][2] += tp * vz;
                    }
                } else if (filt == 2) {
                    // out_1x0_1: acc[0..2] += r * feat1
                    const float4* qp = (const float4*)(f1base +
                        (size_t)(b * FF + fbase) * 3);
                    float4 qa = qp[0], qb = qp[1], qc = qp[2];
                    float q[12] = {qa.x, qa.y, qa.z, qa.w,
                                   qb.x, qb.y, qb.z, qb.w,
                                   qc.x, qc.y, qc.z, qc.w};
#pragma unroll
                    for (int ci = 0; ci < 4; ci++) {
                        acc[ci][0] += r[h][ci] * q[ci * 3 + 0];
                        acc[ci][1] += r[h][ci] * q[ci * 3 + 1];
                        acc[ci][2] += r[h][ci] * q[ci * 3 + 2];
                    }
                } else {
                    // out_1x1_0 (v.q) + out_1x1_1 (v x q)
                    float vx = s_v[bl][0], vy = s_v[bl][1], vz = s_v[bl][2];
                    float n2 = vx * vx + vy * vy + vz * vz;
                    float mk = (n2 < 1e-14f) ? 0.f : 1.f;
                    const float4* qp = (const float4*)(f1base +
                        (size_t)(b * FF + fbase) * 3);
                    float4 qa = qp[0], qb = qp[1], qc = qp[2];
                    float q[12] = {qa.x, qa.y, qa.z, qa.w,
                                   qb.x, qb.y, qb.z, qb.w,
                                   qc.x, qc.y, qc.z, qc.w};
#pragma unroll
                    for (int ci = 0; ci < 4; ci++) {
                        float rm = r[h][ci] * mk;
                        float q0 = q[ci * 3], q1 = q[ci * 3 + 1], q2 = q[ci * 3 + 2];
                        acc[ci][0] += rm * (vx * q0 + vy * q1 + vz * q2);
                        acc[ci][1] += rm * (vy * q2 - vz * q1);
                        acc[ci][2] += rm * (vz * q0 - vx * q2);
                        acc[ci][3] += rm * (vx * q1 - vy * q0);
                    }
                }
            }
        }

        __syncthreads();                 // everyone done reading Ism / s_v
        if (chunk < 3) {
            stsregs();                   // write next chunk
            __syncthreads();
        }
    }

    // ---- reduce across the 8 tb groups (overlay on s_buf) ----
    float* s_red = s_buf;
#pragma unroll
    for (int ci = 0; ci < 4; ci++)
#pragma unroll
        for (int sl = 0; sl < 4; sl++)
            s_red[(tb * 32 + tc) * 16 + ci * 4 + sl] = acc[ci][sl];
    __syncthreads();

    for (int rr = tid; rr < 512; rr += 256) {
        int tcq = rr >> 4, ci = (rr >> 2) & 3, sl = rr & 3;
        float s = 0.f;
#pragma unroll
        for (int g = 0; g < 8; g++)
            s += s_red[(g * 32 + tcq) * 16 + ci * 4 + sl];
        int c = tcq * 4 + ci;
        int ft = c >> 5, f = c & 31;
        int col = -1;
        if (ft == 0)      { if (sl == 0) col = 0; }        // out_0x0_0
        else if (ft == 1) { if (sl < 3)  col = 1 + sl; }   // out_0x1_1
        else if (ft == 2) { if (sl < 3)  col = 4 + sl; }   // out_1x0_1
        else              {              col = 7 + sl; }   // out_1x1_0/1
        if (col >= 0) s_cat[f][col] = s;
    }
    __syncthreads();

    // ---- self-interaction + equivariant activation ----
    if (tid < 32) {
        const int g = tid;
        const float* w0p = w_si0 + g * (2 * FF);
        const float* w1p = w_si1 + g * (3 * FF);
        float si0 = 0.f, sx = 0.f, sy = 0.f, sz = 0.f;
#pragma unroll 8
        for (int f2 = 0; f2 < 32; f2++) {
            const float* c = s_cat[f2];
            si0 += w0p[f2] * c[0] + w0p[32 + f2] * c[7];
            const float wa = w1p[f2], wb = w1p[32 + f2], wc = w1p[64 + f2];
            sx += wa * c[1] + wb * c[4] + wc * c[8];
            sy += wa * c[2] + wb * c[5] + wc * c[9];
            sz += wa * c[3] + wb * c[6] + wc * c[10];
        }
        const float o0v = sspf(si0 + b_act0[g]);
        const float nn  = sx * sx + sy * sy + sz * sz;
        const float n1  = sqrtf(fmaxf(nn, 1e-7f));
        const float a1v = sspf(n1 + b_act1[g]);
        const float sc  = a1v / n1;

        out[(size_t)ma * SI + g] = o0v;                      // o0: (M,A,SI,1)
        float* o1 = out + (size_t)MM * AA * SI + ((size_t)ma * SI + g) * 3;
        o1[0] = sx * sc;
        o1[1] = sy * sc;
        o1[2] = sz * sc;
    }
}

// ---------------------------------------------------------------------------
extern "C" void kernel_launch(void* const* d_in, const int* in_sizes, int n_in,
                              void* d_out, int out_size)
{
    (void)in_sizes; (void)n_in; (void)out_size;

    const float* image   = (const float*)d_in[0];
    const float* vectors = (const float*)d_in[1];
    const float* feat0   = (const float*)d_in[2];
    const float* feat1   = (const float*)d_in[3];

    Wptrs wp;
    for (int filt = 0; filt < 4; filt++) {
        wp.w1[filt] = (const float*)d_in[4 + filt * 4 + 0];
        wp.b1[filt] = (const float*)d_in[4 + filt * 4 + 1];
        wp.w2[filt] = (const float*)d_in[4 + filt * 4 + 2];
        wp.b2[filt] = (const float*)d_in[4 + filt * 4 + 3];
    }
    const float* w_si0  = (const float*)d_in[20];
    const float* w_si1  = (const float*)d_in[21];
    const float* b_act0 = (const float*)d_in[22];
    const float* b_act1 = (const float*)d_in[23];

    prep_kernel<<<32, 256>>>(wp);
    conv_kernel<<<MM * AA, 256>>>(image, vectors, feat0, feat1,
                                  w_si0, w_si1, b_act0, b_act1,
                                  (float*)d_out);
}

// round 12
// speedup vs baseline: 1.2762x; 1.2762x over previous
#include <cuda_runtime.h>
#include <cstddef>

// Problem constants (fixed by the dataset instance)
#define MM   4
#define AA   256
#define RBF  64
#define FF   32
#define HH   32
#define SI   32
#define CC   128   // 4 filters * FF radial columns

// Precombined radial weights, row-major over k: g_Wt[k*CC + c]
__device__ float g_Wt[RBF * CC];
__device__ float g_bias[CC];

struct Wptrs {
    const float* w1[4];
    const float* b1[4];
    const float* w2[4];
    const float* b2[4];
};

// ---------------------------------------------------------------------------
// Precompute W = w1 @ w2 (per filter), bias = b1 @ w2 + b2.
// g_Wt[k][c], c = filt*32 + f  (filt order: 00, 01, 10, 11).
// ---------------------------------------------------------------------------
__global__ void prep_kernel(Wptrs wp) {
    int idx = blockIdx.x * blockDim.x + threadIdx.x;
    if (idx < CC * RBF) {
        int c = idx & (CC - 1);
        int k = idx >> 7;
        int filt = c >> 5;
        int f = c & 31;
        const float* w1 = wp.w1[filt];
        const float* w2 = wp.w2[filt];
        float s = 0.f;
#pragma unroll
        for (int h = 0; h < HH; h++)
            s += w1[k * HH + h] * w2[h * FF + f];
        g_Wt[k * CC + c] = s;
        if (k == 0) {
            float bs = wp.b2[filt][f];
            const float* b1 = wp.b1[filt];
#pragma unroll
            for (int h = 0; h < HH; h++)
                bs += b1[h] * w2[h * FF + f];
            g_bias[c] = bs;
        }
    }
}

// ---------------------------------------------------------------------------
// Packed fp32x2 helpers (Blackwell FFMA2 — PTX-only path)
// ---------------------------------------------------------------------------
typedef unsigned long long u64;

__device__ __forceinline__ u64 ffma2(u64 a, u64 b, u64 c) {
    u64 d;
    asm("fma.rn.f32x2 %0, %1, %2, %3;" : "=l"(d) : "l"(a), "l"(b), "l"(c));
    return d;
}
__device__ __forceinline__ u64 splat2(float x) {
    u64 d;
    asm("mov.b64 %0, {%1, %1};" : "=l"(d) : "f"(x));
    return d;
}
__device__ __forceinline__ float2 unpk(u64 a) {
    float2 r;
    asm("mov.b64 {%0, %1}, %2;" : "=f"(r.x), "=f"(r.y) : "l"(a));
    return r;
}
__device__ __forceinline__ float sspf(float x) {
    return logf(0.5f * expf(x) + 0.5f);   // shifted softplus
}

#define SACC_STRIDE 257   // 32-float-row pad breaks bank aliasing in reduce

// ---------------------------------------------------------------------------
// Main fused kernel: one block per (m, a).  256 threads.
//   tc = tid>>4 (0..15): 8 radial columns c = 8*tc..8*tc+7 (one filter/warp)
//   tb = tid&15 (0..15): 8 neighbor rows per 128-row chunk
// 8b x 8c register tile: 64B loaded per 64 FMA (1.0 B/FMA) -> FMA-bound.
// W via LDG (sector-dedup, ~free); image via LDS from transposed smem tile.
// ---------------------------------------------------------------------------
__global__ void __launch_bounds__(256, 2) conv_kernel(
    const float* __restrict__ image,
    const float* __restrict__ vectors,
    const float* __restrict__ feat0,
    const float* __restrict__ feat1,
    const float* __restrict__ w_si0,
    const float* __restrict__ w_si1,
    const float* __restrict__ b_act0,
    const float* __restrict__ b_act1,
    float* __restrict__ out)
{
    extern __shared__ float sm[];
    float* Ism   = sm;                          // [64][128]  (32 KB)
    float* s_acc = sm + 64 * 128;               // [32][257]  (~32 KB)
    float* s_v   = s_acc + 32 * SACC_STRIDE;    // [256][4]
    float* s_cat = s_v + 256 * 4;               // [32][12]

    const int ma  = blockIdx.x;        // m*AA + a
    const int m   = ma >> 8;
    const int tid = threadIdx.x;
    const int tc  = tid >> 4;          // 0..15
    const int tb  = tid & 15;          // 0..15
    const int filt  = tc >> 2;         // 0..3  (warp-uniform)
    const int c0    = tc * 8;
    const int fbase = (tc & 3) * 8;

    const float* imgbase = image   + (size_t)ma * (AA * RBF);
    const float* vbase   = vectors + (size_t)ma * (AA * 3);
    const float* f0base  = feat0   + (size_t)m  * (AA * FF);
    const float* f1base  = feat1   + (size_t)m  * (AA * FF * 3);

    // all 256 vectors once
    for (int u = tid; u < 768; u += 256)
        s_v[(u / 3) * 4 + (u % 3)] = vbase[u];

    float bias[8];
    {
        float4 ba = *(const float4*)(g_bias + c0);
        float4 bb = *(const float4*)(g_bias + c0 + 4);
        bias[0] = ba.x; bias[1] = ba.y; bias[2] = ba.z; bias[3] = ba.w;
        bias[4] = bb.x; bias[5] = bb.y; bias[6] = bb.z; bias[7] = bb.w;
    }

    const int sb  = tid & 127;         // staged row within chunk
    const int skq = tid >> 7;          // 0..1: which 32-k half

    const float4* wrow = (const float4*)(g_Wt + c0);

    for (int chunk = 0; chunk < 2; chunk++) {
        __syncthreads();
        // ---- stage 128 rows x 64 k, transposed into Ism[k][b] ----
        {
            const float4* src = (const float4*)(imgbase +
                (size_t)(chunk * 128 + sb) * RBF + skq * 32);
#pragma unroll
            for (int j = 0; j < 8; j++) {
                float4 v = __ldg(src + j);
                const int k0 = skq * 32 + j * 4;
                Ism[(k0 + 0) * 128 + sb] = v.x;
                Ism[(k0 + 1) * 128 + sb] = v.y;
                Ism[(k0 + 2) * 128 + sb] = v.z;
                Ism[(k0 + 3) * 128 + sb] = v.w;
            }
        }
        __syncthreads();

        // ---- 8b x 8c register-tiled GEMM over k=64 ----
        u64 t[8][4];
#pragma unroll
        for (int ci = 0; ci < 8; ci++)
#pragma unroll
            for (int bp = 0; bp < 4; bp++) t[ci][bp] = 0ULL;

#pragma unroll 8
        for (int k = 0; k < 64; k++) {
            const u64* ip = (const u64*)(Ism + k * 128 + tb * 8);
            u64 i0 = ip[0], i1 = ip[1], i2 = ip[2], i3 = ip[3];
            float4 wa = __ldg(wrow + k * 32);
            float4 wb = __ldg(wrow + k * 32 + 1);
            u64 w;
            w = splat2(wa.x);
            t[0][0]=ffma2(i0,w,t[0][0]); t[0][1]=ffma2(i1,w,t[0][1]);
            t[0][2]=ffma2(i2,w,t[0][2]); t[0][3]=ffma2(i3,w,t[0][3]);
            w = splat2(wa.y);
            t[1][0]=ffma2(i0,w,t[1][0]); t[1][1]=ffma2(i1,w,t[1][1]);
            t[1][2]=ffma2(i2,w,t[1][2]); t[1][3]=ffma2(i3,w,t[1][3]);
            w = splat2(wa.z);
            t[2][0]=ffma2(i0,w,t[2][0]); t[2][1]=ffma2(i1,w,t[2][1]);
            t[2][2]=ffma2(i2,w,t[2][2]); t[2][3]=ffma2(i3,w,t[2][3]);
            w = splat2(wa.w);
            t[3][0]=ffma2(i0,w,t[3][0]); t[3][1]=ffma2(i1,w,t[3][1]);
            t[3][2]=ffma2(i2,w,t[3][2]); t[3][3]=ffma2(i3,w,t[3][3]);
            w = splat2(wb.x);
            t[4][0]=ffma2(i0,w,t[4][0]); t[4][1]=ffma2(i1,w,t[4][1]);
            t[4][2]=ffma2(i2,w,t[4][2]); t[4][3]=ffma2(i3,w,t[4][3]);
            w = splat2(wb.y);
            t[5][0]=ffma2(i0,w,t[5][0]); t[5][1]=ffma2(i1,w,t[5][1]);
            t[5][2]=ffma2(i2,w,t[5][2]); t[5][3]=ffma2(i3,w,t[5][3]);
            w = splat2(wb.z);
            t[6][0]=ffma2(i0,w,t[6][0]); t[6][1]=ffma2(i1,w,t[6][1]);
            t[6][2]=ffma2(i2,w,t[6][2]); t[6][3]=ffma2(i3,w,t[6][3]);
            w = splat2(wb.w);
            t[7][0]=ffma2(i0,w,t[7][0]); t[7][1]=ffma2(i1,w,t[7][1]);
            t[7][2]=ffma2(i2,w,t[7][2]); t[7][3]=ffma2(i3,w,t[7][3]);
        }

        // ---- contraction over this chunk's 8 b rows ----
        float a[32];
#pragma unroll
        for (int j = 0; j < 32; j++) a[j] = 0.f;

#pragma unroll
        for (int bp = 0; bp < 4; bp++) {
            float r0[8], r1[8];
#pragma unroll
            for (int ci = 0; ci < 8; ci++) {
                float2 u = unpk(t[ci][bp]);
                r0[ci] = u.x + bias[ci];
                r1[ci] = u.y + bias[ci];
            }
#pragma unroll
            for (int h = 0; h < 2; h++) {
                float rr8[8];
#pragma unroll
                for (int ci = 0; ci < 8; ci++) rr8[ci] = h ? r1[ci] : r0[ci];
                const int bl = chunk * 128 + tb * 8 + bp * 2 + h;

                if (filt == 0) {
                    float4 pa = __ldg((const float4*)(f0base + bl * FF + fbase));
                    float4 pb = __ldg((const float4*)(f0base + bl * FF + fbase) + 1);
                    float p[8] = {pa.x, pa.y, pa.z, pa.w, pb.x, pb.y, pb.z, pb.w};
#pragma unroll
                    for (int ci = 0; ci < 8; ci++)
                        a[ci * 4] += rr8[ci] * p[ci];
                } else if (filt == 1) {
                    float vx = s_v[bl*4], vy = s_v[bl*4+1], vz = s_v[bl*4+2];
                    float n2 = vx*vx + vy*vy + vz*vz;
                    float mk = (n2 < 1e-14f) ? 0.f : 1.f;
                    float4 pa = __ldg((const float4*)(f0base + bl * FF + fbase));
                    float4 pb = __ldg((const float4*)(f0base + bl * FF + fbase) + 1);
                    float p[8] = {pa.x, pa.y, pa.z, pa.w, pb.x, pb.y, pb.z, pb.w};
#pragma unroll
                    for (int ci = 0; ci < 8; ci++) {
                        float tp = rr8[ci] * mk * p[ci];
                        a[ci*4+0] += tp * vx;
                        a[ci*4+1] += tp * vy;
                        a[ci*4+2] += tp * vz;
                    }
                } else if (filt == 2) {
#pragma unroll
                    for (int half = 0; half < 2; half++) {
                        const float4* qp = (const float4*)(f1base +
                            (size_t)(bl * FF + fbase + half * 4) * 3);
                        float4 qa = __ldg(qp), qb = __ldg(qp+1), qc = __ldg(qp+2);
                        float q[12] = {qa.x,qa.y,qa.z,qa.w, qb.x,qb.y,qb.z,qb.w,
                                       qc.x,qc.y,qc.z,qc.w};
#pragma unroll
                        for (int c2 = 0; c2 < 4; c2++) {
                            int ci = half * 4 + c2;
                            a[ci*4+0] += rr8[ci] * q[c2*3+0];
                            a[ci*4+1] += rr8[ci] * q[c2*3+1];
                            a[ci*4+2] += rr8[ci] * q[c2*3+2];
                        }
                    }
                } else {
                    float vx = s_v[bl*4], vy = s_v[bl*4+1], vz = s_v[bl*4+2];
                    float n2 = vx*vx + vy*vy + vz*vz;
                    float mk = (n2 < 1e-14f) ? 0.f : 1.f;
#pragma unroll
                    for (int half = 0; half < 2; half++) {
                        const float4* qp = (const float4*)(f1base +
                            (size_t)(bl * FF + fbase + half * 4) * 3);
                        float4 qa = __ldg(qp), qb = __ldg(qp+1), qc = __ldg(qp+2);
                        float q[12] = {qa.x,qa.y,qa.z,qa.w, qb.x,qb.y,qb.z,qb.w,
                                       qc.x,qc.y,qc.z,qc.w};
#pragma unroll
                        for (int c2 = 0; c2 < 4; c2++) {
                            int ci = half * 4 + c2;
                            float rm = rr8[ci] * mk;
                            float q0 = q[c2*3], q1 = q[c2*3+1], q2 = q[c2*3+2];
                            a[ci*4+0] += rm * (vx*q0 + vy*q1 + vz*q2);   // v.q
                            a[ci*4+1] += rm * (vy*q2 - vz*q1);           // v x q
                            a[ci*4+2] += rm * (vz*q0 - vx*q2);
                            a[ci*4+3] += rm * (vx*q1 - vy*q0);
                        }
                    }
                }
            }
        }

        if (chunk == 0) {
#pragma unroll
            for (int j = 0; j < 32; j++)
                s_acc[j * SACC_STRIDE + tid] = a[j];
        } else {
#pragma unroll
            for (int j = 0; j < 32; j++)
                s_acc[j * SACC_STRIDE + tid] += a[j];
        }
    }
    __syncthreads();

    // ---- cross-tb reduction (16 partials per (c, slot)) ----
    for (int rr = tid; rr < 512; rr += 256) {
        const int c = rr >> 2, sl = rr & 3;
        const int tc2 = c >> 3, ci = c & 7;
        const int j = ci * 4 + sl;
        float s = 0.f;
#pragma unroll
        for (int g = 0; g < 16; g++)
            s += s_acc[j * SACC_STRIDE + tc2 * 16 + g];
        const int ft = c >> 5, f = c & 31;
        int col = -1;
        if (ft == 0)      { if (sl == 0) col = 0; }        // out_0x0_0
        else if (ft == 1) { if (sl < 3)  col = 1 + sl; }   // out_0x1_1
        else if (ft == 2) { if (sl < 3)  col = 4 + sl; }   // out_1x0_1
        else              {              col = 7 + sl; }   // out_1x1_0/1
        if (col >= 0) s_cat[f * 12 + col] = s;
    }
    __syncthreads();

    // ---- self-interaction + equivariant activation ----
    if (tid < 32) {
        const int g = tid;
        const float* w0p = w_si0 + g * (2 * FF);
        const float* w1p = w_si1 + g * (3 * FF);
        float si0 = 0.f, sx = 0.f, sy = 0.f, sz = 0.f;
#pragma unroll 8
        for (int f2 = 0; f2 < 32; f2++) {
            const float* c = s_cat + f2 * 12;
            si0 += w0p[f2] * c[0] + w0p[32 + f2] * c[7];
            const float wa = w1p[f2], wb = w1p[32 + f2], wc = w1p[64 + f2];
            sx += wa * c[1] + wb * c[4] + wc * c[8];
            sy += wa * c[2] + wb * c[5] + wc * c[9];
            sz += wa * c[3] + wb * c[6] + wc * c[10];
        }
        const float o0v = sspf(si0 + b_act0[g]);
        const float nn  = sx * sx + sy * sy + sz * sz;
        const float n1  = sqrtf(fmaxf(nn, 1e-7f));
        const float a1v = sspf(n1 + b_act1[g]);
        const float sc  = a1v / n1;

        out[(size_t)ma * SI + g] = o0v;                      // o0: (M,A,SI,1)
        float* o1 = out + (size_t)MM * AA * SI + ((size_t)ma * SI + g) * 3;
        o1[0] = sx * sc;
        o1[1] = sy * sc;
        o1[2] = sz * sc;
    }
}

// ---------------------------------------------------------------------------
extern "C" void kernel_launch(void* const* d_in, const int* in_sizes, int n_in,
                              void* d_out, int out_size)
{
    (void)in_sizes; (void)n_in; (void)out_size;

    const float* image   = (const float*)d_in[0];
    const float* vectors = (const float*)d_in[1];
    const float* feat0   = (const float*)d_in[2];
    const float* feat1   = (const float*)d_in[3];

    Wptrs wp;
    for (int filt = 0; filt < 4; filt++) {
        wp.w1[filt] = (const float*)d_in[4 + filt * 4 + 0];
        wp.b1[filt] = (const float*)d_in[4 + filt * 4 + 1];
        wp.w2[filt] = (const float*)d_in[4 + filt * 4 + 2];
        wp.b2[filt] = (const float*)d_in[4 + filt * 4 + 3];
    }
    const float* w_si0  = (const float*)d_in[20];
    const float* w_si1  = (const float*)d_in[21];
    const float* b_act0 = (const float*)d_in[22];
    const float* b_act1 = (const float*)d_in[23];

    const int smem_bytes = (64 * 128 + 32 * SACC_STRIDE + 256 * 4 + 32 * 12)
                           * (int)sizeof(float);
    static int attr_set = 0;
    cudaFuncSetAttribute(conv_kernel,
                         cudaFuncAttributeMaxDynamicSharedMemorySize,
                         smem_bytes);
    (void)attr_set;

    prep_kernel<<<32, 256>>>(wp);
    conv_kernel<<<MM * AA, 256, smem_bytes>>>(image, vectors, feat0, feat1,
                                              w_si0, w_si1, b_act0, b_act1,
                                              (float*)d_out);
}

// round 13
// speedup vs baseline: 2.0499x; 1.6062x over previous
#include <cuda_runtime.h>
#include <cstddef>

// Problem constants (fixed by the dataset instance)
#define MM   4
#define AA   256
#define RBF  64
#define FF   32
#define HH   32
#define SI   32
#define CC   128   // 4 filters * FF radial columns

// Precombined radial weights, row-major over k: g_Wt[k*CC + c]
__device__ float g_Wt[RBF * CC];
__device__ float g_bias[CC];
// feat1 transposed to component-major planes: g_f1t[m][d][b][f]
__device__ float g_f1t[MM * 3 * AA * FF];

struct Wptrs {
    const float* w1[4];
    const float* b1[4];
    const float* w2[4];
    const float* b2[4];
};

// ---------------------------------------------------------------------------
// Precompute W = w1 @ w2 (per filter), bias = b1 @ w2 + b2.
// g_Wt[k][c], c = filt*32 + f  (filt order: 00, 01, 10, 11).
// ---------------------------------------------------------------------------
__global__ void prep_kernel(Wptrs wp) {
    int idx = blockIdx.x * blockDim.x + threadIdx.x;
    if (idx < CC * RBF) {
        int c = idx & (CC - 1);
        int k = idx >> 7;
        int filt = c >> 5;
        int f = c & 31;
        const float* w1 = wp.w1[filt];
        const float* w2 = wp.w2[filt];
        float s = 0.f;
#pragma unroll
        for (int h = 0; h < HH; h++)
            s += w1[k * HH + h] * w2[h * FF + f];
        g_Wt[k * CC + c] = s;
        if (k == 0) {
            float bs = wp.b2[filt][f];
            const float* b1 = wp.b1[filt];
#pragma unroll
            for (int h = 0; h < HH; h++)
                bs += b1[h] * w2[h * FF + f];
            g_bias[c] = bs;
        }
    }
}

// Transpose feat1 [m][b][f][3] -> g_f1t[m][d][b][f]
__global__ void prep_f1t(const float* __restrict__ feat1) {
    int idx = blockIdx.x * blockDim.x + threadIdx.x;   // over m*3*256*32
    if (idx < MM * 3 * AA * FF) {
        int f = idx & 31;
        int b = (idx >> 5) & 255;
        int d = (idx >> 13) % 3;
        int m = idx / (3 * AA * FF);
        g_f1t[idx] = feat1[(((size_t)m * AA + b) * FF + f) * 3 + d];
    }
}

// ---------------------------------------------------------------------------
// Packed fp32x2 helpers (Blackwell FFMA2 — PTX-only path)
// ---------------------------------------------------------------------------
typedef unsigned long long u64;

__device__ __forceinline__ u64 ffma2(u64 a, u64 b, u64 c) {
    u64 d;
    asm("fma.rn.f32x2 %0, %1, %2, %3;" : "=l"(d) : "l"(a), "l"(b), "l"(c));
    return d;
}
__device__ __forceinline__ u64 splat2(float x) {
    u64 d;
    asm("mov.b64 %0, {%1, %1};" : "=l"(d) : "f"(x));
    return d;
}
__device__ __forceinline__ float2 unpk(u64 a) {
    float2 r;
    asm("mov.b64 {%0, %1}, %2;" : "=f"(r.x), "=f"(r.y) : "l"(a));
    return r;
}
__device__ __forceinline__ float sspf(float x) {
    return logf(0.5f * expf(x) + 0.5f);   // shifted softplus
}

// smem floats: R(128*128, aliases Ism 64*128) + v(256*4) + red(8*32*12) + cat(32*12)
#define SMEM_FLOATS (128 * 128 + 256 * 4 + 8 * 32 * 12 + 32 * 12)

// ---------------------------------------------------------------------------
// Main fused kernel: one block per (m, a).  256 threads, 2 CTAs/SM.
// Phase A (GEMM): tc=tid>>4 owns c=8tc..8tc+7; tb=tid&15 owns
//   b in {4tb..4tb+3} U {64+4tb..+3}  -> conflict-free LDS.128.
// Radial tile R[128b][128c] stored to smem with XOR swizzle (cq ^= (b>>2)&7).
// Phase B (contraction): warp w owns 16 b-rows, lane = f -> all feat loads
//   perfectly coalesced; R read back conflict-free via the same swizzle.
// ---------------------------------------------------------------------------
__global__ void __launch_bounds__(256, 2) conv_kernel(
    const float* __restrict__ image,
    const float* __restrict__ vectors,
    const float* __restrict__ feat0,
    const float* __restrict__ w_si0,
    const float* __restrict__ w_si1,
    const float* __restrict__ b_act0,
    const float* __restrict__ b_act1,
    float* __restrict__ out)
{
    extern __shared__ float sm[];
    float* s_R   = sm;                       // [128][128] swizzled (64 KB)
    float* Ism   = sm;                       // [64][128] aliases R (dead pre-R)
    float* s_v   = sm + 128 * 128;           // [256][4]
    float* s_red = s_v + 256 * 4;            // [8][32][12]
    float* s_cat = s_red + 8 * 32 * 12;      // [32][12]

    const int ma   = blockIdx.x;             // m*AA + a
    const int m    = ma >> 8;
    const int tid  = threadIdx.x;
    const int tc   = tid >> 4;               // 0..15 (GEMM c-group)
    const int tb   = tid & 15;               // 0..15 (GEMM b-group)
    const int c0   = tc * 8;
    const int w    = tid >> 5;               // warp 0..7
    const int lane = tid & 31;               // = f in phase B

    const float* imgbase = image   + (size_t)ma * (AA * RBF);
    const float* vbase   = vectors + (size_t)ma * (AA * 3);
    const float* f0base  = feat0   + (size_t)m  * (AA * FF);
    const float* f1t0 = g_f1t + (size_t)(m * 3 + 0) * (AA * FF);
    const float* f1t1 = g_f1t + (size_t)(m * 3 + 1) * (AA * FF);
    const float* f1t2 = g_f1t + (size_t)(m * 3 + 2) * (AA * FF);

    // all 256 neighbor vectors (padded to 4)
    for (int u = tid; u < 768; u += 256)
        s_v[(u / 3) * 4 + (u % 3)] = vbase[u];

    float bias[8];
    {
        float4 ba = *(const float4*)(g_bias + c0);
        float4 bb = *(const float4*)(g_bias + c0 + 4);
        bias[0] = ba.x; bias[1] = ba.y; bias[2] = ba.z; bias[3] = ba.w;
        bias[4] = bb.x; bias[5] = bb.y; bias[6] = bb.z; bias[7] = bb.w;
    }

    float a[11];
#pragma unroll
    for (int j = 0; j < 11; j++) a[j] = 0.f;

    const int sb  = tid & 127;               // staging: b row within chunk
    const int skq = tid >> 7;                // staging: 32-k half
    const float4* wrow = (const float4*)(g_Wt + c0);

    for (int chunk = 0; chunk < 2; chunk++) {
        __syncthreads();   // prior contraction finished reading R
        // ---- stage 128 rows x 64 k, transposed into Ism[k][b] ----
        {
            const float4* src = (const float4*)(imgbase +
                (size_t)(chunk * 128 + sb) * RBF + skq * 32);
#pragma unroll
            for (int j = 0; j < 8; j++) {
                float4 v = __ldg(src + j);
                const int k0 = skq * 32 + j * 4;
                Ism[(k0 + 0) * 128 + sb] = v.x;
                Ism[(k0 + 1) * 128 + sb] = v.y;
                Ism[(k0 + 2) * 128 + sb] = v.z;
                Ism[(k0 + 3) * 128 + sb] = v.w;
            }
        }
        __syncthreads();

        // ---- 8b x 8c register-tiled GEMM over k=64 (conflict-free LDS) ----
        u64 t[8][4];
#pragma unroll
        for (int ci = 0; ci < 8; ci++)
#pragma unroll
            for (int bp = 0; bp < 4; bp++) t[ci][bp] = 0ULL;

#pragma unroll 8
        for (int k = 0; k < 64; k++) {
            const u64* ipA = (const u64*)(Ism + k * 128 + tb * 4);
            const u64* ipB = (const u64*)(Ism + k * 128 + 64 + tb * 4);
            u64 i0 = ipA[0], i1 = ipA[1];    // b = 4tb..4tb+3
            u64 i2 = ipB[0], i3 = ipB[1];    // b = 64+4tb..+3
            float4 wa = __ldg(wrow + k * 32);
            float4 wb = __ldg(wrow + k * 32 + 1);
            u64 ww;
            ww = splat2(wa.x);
            t[0][0]=ffma2(i0,ww,t[0][0]); t[0][1]=ffma2(i1,ww,t[0][1]);
            t[0][2]=ffma2(i2,ww,t[0][2]); t[0][3]=ffma2(i3,ww,t[0][3]);
            ww = splat2(wa.y);
            t[1][0]=ffma2(i0,ww,t[1][0]); t[1][1]=ffma2(i1,ww,t[1][1]);
            t[1][2]=ffma2(i2,ww,t[1][2]); t[1][3]=ffma2(i3,ww,t[1][3]);
            ww = splat2(wa.z);
            t[2][0]=ffma2(i0,ww,t[2][0]); t[2][1]=ffma2(i1,ww,t[2][1]);
            t[2][2]=ffma2(i2,ww,t[2][2]); t[2][3]=ffma2(i3,ww,t[2][3]);
            ww = splat2(wa.w);
            t[3][0]=ffma2(i0,ww,t[3][0]); t[3][1]=ffma2(i1,ww,t[3][1]);
            t[3][2]=ffma2(i2,ww,t[3][2]); t[3][3]=ffma2(i3,ww,t[3][3]);
            ww = splat2(wb.x);
            t[4][0]=ffma2(i0,ww,t[4][0]); t[4][1]=ffma2(i1,ww,t[4][1]);
            t[4][2]=ffma2(i2,ww,t[4][2]); t[4][3]=ffma2(i3,ww,t[4][3]);
            ww = splat2(wb.y);
            t[5][0]=ffma2(i0,ww,t[5][0]); t[5][1]=ffma2(i1,ww,t[5][1]);
            t[5][2]=ffma2(i2,ww,t[5][2]); t[5][3]=ffma2(i3,ww,t[5][3]);
            ww = splat2(wb.z);
            t[6][0]=ffma2(i0,ww,t[6][0]); t[6][1]=ffma2(i1,ww,t[6][1]);
            t[6][2]=ffma2(i2,ww,t[6][2]); t[6][3]=ffma2(i3,ww,t[6][3]);
            ww = splat2(wb.w);
            t[7][0]=ffma2(i0,ww,t[7][0]); t[7][1]=ffma2(i1,ww,t[7][1]);
            t[7][2]=ffma2(i2,ww,t[7][2]); t[7][3]=ffma2(i3,ww,t[7][3]);
        }
        __syncthreads();   // Ism dead; safe to clobber with R

        // ---- write radial tile R[b][c] (swizzled, conflict-free STS.128) ----
#pragma unroll
        for (int bp = 0; bp < 4; bp++) {
            const int bBase = tb * 4 + ((bp >> 1) << 6) + (bp & 1) * 2;
#pragma unroll
            for (int h = 0; h < 2; h++) {
                const int b = bBase + h;
                const int xw = (b >> 2) & 7;
                float4 lo, hi;
                {
                    float2 u0 = unpk(t[0][bp]), u1 = unpk(t[1][bp]);
                    float2 u2 = unpk(t[2][bp]), u3 = unpk(t[3][bp]);
                    lo.x = (h ? u0.y : u0.x) + bias[0];
                    lo.y = (h ? u1.y : u1.x) + bias[1];
                    lo.z = (h ? u2.y : u2.x) + bias[2];
                    lo.w = (h ? u3.y : u3.x) + bias[3];
                    float2 u4 = unpk(t[4][bp]), u5 = unpk(t[5][bp]);
                    float2 u6 = unpk(t[6][bp]), u7 = unpk(t[7][bp]);
                    hi.x = (h ? u4.y : u4.x) + bias[4];
                    hi.y = (h ? u5.y : u5.x) + bias[5];
                    hi.z = (h ? u6.y : u6.x) + bias[6];
                    hi.w = (h ? u7.y : u7.x) + bias[7];
                }
                const int cqLo = (tc * 2) ^ xw;
                const int cqHi = (tc * 2 + 1) ^ xw;
                *(float4*)(s_R + b * 128 + cqLo * 4) = lo;
                *(float4*)(s_R + b * 128 + cqHi * 4) = hi;
            }
        }
        __syncthreads();

        // ---- contraction: warp w owns 16 b-rows; lane = f ----
#pragma unroll 4
        for (int i = 0; i < 16; i++) {
            const int bl = w * 16 + i;           // row in R
            const int b  = chunk * 128 + bl;     // global neighbor
            const float p0 = __ldg(f0base + b * FF + lane);
            const float q0 = __ldg(f1t0 + b * FF + lane);
            const float q1 = __ldg(f1t1 + b * FF + lane);
            const float q2 = __ldg(f1t2 + b * FF + lane);
            const float vx = s_v[b * 4], vy = s_v[b * 4 + 1], vz = s_v[b * 4 + 2];
            const int xw  = (bl >> 2) & 7;
            const int off = (((lane >> 2) ^ xw) << 2) + (lane & 3);
            const float* rp = s_R + bl * 128 + off;
            const float r00 = rp[0];
            const float r01 = rp[32];
            const float r10 = rp[64];
            const float r11 = rp[96];
            const float n2 = vx * vx + vy * vy + vz * vz;
            const float mk = (n2 < 1e-14f) ? 0.f : 1.f;

            a[0] += r00 * p0;                        // out_0x0_0
            const float t1 = r01 * mk * p0;          // out_0x1_1
            a[1] += t1 * vx;  a[2] += t1 * vy;  a[3] += t1 * vz;
            a[4] += r10 * q0; a[5] += r10 * q1; a[6] += r10 * q2;  // out_1x0_1
            const float rm = r11 * mk;               // out_1x1_0 / _1
            a[7]  += rm * (vx * q0 + vy * q1 + vz * q2);
            a[8]  += rm * (vy * q2 - vz * q1);
            a[9]  += rm * (vz * q0 - vx * q2);
            a[10] += rm * (vx * q1 - vy * q0);
        }
    }

    // ---- cross-warp reduction ----
#pragma unroll
    for (int j = 0; j < 11; j++) s_red[(w * 32 + lane) * 12 + j] = a[j];
    __syncthreads();

    for (int idx = tid; idx < 352; idx += 256) {
        const int f = idx / 11, col = idx % 11;
        float s = 0.f;
#pragma unroll
        for (int g = 0; g < 8; g++)
            s += s_red[(g * 32 + f) * 12 + col];
        s_cat[f * 12 + col] = s;
    }
    __syncthreads();

    // ---- self-interaction + equivariant activation ----
    if (tid < 32) {
        const int g = tid;
        const float* w0p = w_si0 + g * (2 * FF);
        const float* w1p = w_si1 + g * (3 * FF);
        float si0 = 0.f, sx = 0.f, sy = 0.f, sz = 0.f;
#pragma unroll 8
        for (int f2 = 0; f2 < 32; f2++) {
            const float* c = s_cat + f2 * 12;
            si0 += w0p[f2] * c[0] + w0p[32 + f2] * c[7];
            const float wa = w1p[f2], wb = w1p[32 + f2], wc = w1p[64 + f2];
            sx += wa * c[1] + wb * c[4] + wc * c[8];
            sy += wa * c[2] + wb * c[5] + wc * c[9];
            sz += wa * c[3] + wb * c[6] + wc * c[10];
        }
        const float o0v = sspf(si0 + b_act0[g]);
        const float nn  = sx * sx + sy * sy + sz * sz;
        const float n1  = sqrtf(fmaxf(nn, 1e-7f));
        const float a1v = sspf(n1 + b_act1[g]);
        const float sc  = a1v / n1;

        out[(size_t)ma * SI + g] = o0v;                      // o0: (M,A,SI,1)
        float* o1 = out + (size_t)MM * AA * SI + ((size_t)ma * SI + g) * 3;
        o1[0] = sx * sc;
        o1[1] = sy * sc;
        o1[2] = sz * sc;
    }
}

// ---------------------------------------------------------------------------
extern "C" void kernel_launch(void* const* d_in, const int* in_sizes, int n_in,
                              void* d_out, int out_size)
{
    (void)in_sizes; (void)n_in; (void)out_size;

    const float* image   = (const float*)d_in[0];
    const float* vectors = (const float*)d_in[1];
    const float* feat0   = (const float*)d_in[2];
    const float* feat1   = (const float*)d_in[3];

    Wptrs wp;
    for (int filt = 0; filt < 4; filt++) {
        wp.w1[filt] = (const float*)d_in[4 + filt * 4 + 0];
        wp.b1[filt] = (const float*)d_in[4 + filt * 4 + 1];
        wp.w2[filt] = (const float*)d_in[4 + filt * 4 + 2];
        wp.b2[filt] = (const float*)d_in[4 + filt * 4 + 3];
    }
    const float* w_si0  = (const float*)d_in[20];
    const float* w_si1  = (const float*)d_in[21];
    const float* b_act0 = (const float*)d_in[22];
    const float* b_act1 = (const float*)d_in[23];

    const int smem_bytes = SMEM_FLOATS * (int)sizeof(float);
    cudaFuncSetAttribute(conv_kernel,
                         cudaFuncAttributeMaxDynamicSharedMemorySize,
                         smem_bytes);

    prep_kernel<<<32, 256>>>(wp);
    prep_f1t<<<(MM * 3 * AA * FF + 255) / 256, 256>>>(feat1);
    conv_kernel<<<MM * AA, 256, smem_bytes>>>(image, vectors, feat0,
                                              w_si0, w_si1, b_act0, b_act1,
                                              (float*)d_out);
}